// round 14
// baseline (speedup 1.0000x reference)
#include <cuda_runtime.h>
#include <cuda_fp16.h>
#include <cstdint>

#define N_NODES 100000
#define N_EDGES 1600000
#define HID 128
#define NGRAPH 64
#define NCLASS 10
#define SCAN_NB ((N_NODES + 1023) / 1024)
#define NTILES128 ((N_NODES + 127) / 128)
#define PROJ_GRID 148

// ---------------- scratch (no allocations allowed) ----------------
__device__ uint4  g_Z[N_NODES * 16];      // h@Wl^T, fp16
__device__ uint4  g_Y[N_NODES * 16];      // h@Wr^T + b, fp16
__device__ uint4  g_h[N_NODES * 16];      // layer intermediate h, fp16
__device__ uint4  g_Bh[3 * 4096];         // per-layer [Wl;Wr] fp16 hi
__device__ uint4  g_Bl[3 * 4096];         // per-layer fp16 lo
__device__ int    g_cnt[N_NODES];
__device__ int    g_off[N_NODES + 1];
__device__ int    g_ssrc[N_EDGES];
__device__ int    g_bsum[1024];
__device__ float  g_pool[NGRAPH * HID];

// ---------------- prep: zero cnt/pool + weight fp16 hi/lo split (one launch) --------
__global__ void k_prep(const float* __restrict__ W1l, const float* __restrict__ W1r,
                       const float* __restrict__ W2l, const float* __restrict__ W2r,
                       const float* __restrict__ W3l, const float* __restrict__ W3r,
                       __half* __restrict__ Bh, __half* __restrict__ Bl) {
    int idx = blockIdx.x * blockDim.x + threadIdx.x;
    if (idx < N_NODES) g_cnt[idx] = 0;
    if (idx < NGRAPH * HID) g_pool[idx] = 0.0f;
    if (idx < 3 * 32768) {
        int layer = idx >> 15;
        int r = idx & 32767;
        int o = r >> 7, k = r & 127;
        const float* W = (layer == 0) ? ((o < 128) ? W1l : W1r)
                       : (layer == 1) ? ((o < 128) ? W2l : W2r)
                                      : ((o < 128) ? W3l : W3r);
        float f = W[(o & 127) * 128 + k];
        __half h = __float2half_rn(f);
        Bh[idx] = h;
        Bl[idx] = __float2half_rn(f - __half2float(h));
    }
}

// ---------------- CSR build ----------------
__global__ void k_hist(const int* __restrict__ dst) {
    int e = blockIdx.x * blockDim.x + threadIdx.x;
    if (e < N_EDGES) atomicAdd(&g_cnt[dst[e]], 1);
}
__global__ void k_scan1() {
    __shared__ int sh[1024];
    int t = threadIdx.x;
    int i = blockIdx.x * 1024 + t;
    int v = (i < N_NODES) ? g_cnt[i] : 0;
    sh[t] = v;
    __syncthreads();
    for (int d = 1; d < 1024; d <<= 1) {
        int tv = (t >= d) ? sh[t - d] : 0;
        __syncthreads();
        sh[t] += tv;
        __syncthreads();
    }
    if (i < N_NODES) g_off[i] = sh[t] - v;
    if (t == 1023) g_bsum[blockIdx.x] = sh[1023];
}
__global__ void k_scan2() {
    __shared__ int sh[1024];
    int t = threadIdx.x;
    int v = (t < SCAN_NB) ? g_bsum[t] : 0;
    sh[t] = v;
    __syncthreads();
    for (int d = 1; d < 1024; d <<= 1) {
        int tv = (t >= d) ? sh[t - d] : 0;
        __syncthreads();
        sh[t] += tv;
        __syncthreads();
    }
    if (t < SCAN_NB) g_bsum[t] = sh[t] - v;
}
__global__ void k_scan3() {
    int i = blockIdx.x * blockDim.x + threadIdx.x;
    if (i < N_NODES) {
        int o = g_off[i] + g_bsum[i >> 10];
        g_off[i] = o;
        g_cnt[i] = o;
    }
    if (i == 0) g_off[N_NODES] = N_EDGES;
}
__global__ void k_scatter(const int* __restrict__ src, const int* __restrict__ dst) {
    int e = blockIdx.x * blockDim.x + threadIdx.x;
    if (e < N_EDGES) {
        int d = dst[e];
        int pos = atomicAdd(&g_cnt[d], 1);
        g_ssrc[pos] = src[e];
    }
}

// ---------------- GEMM machinery ----------------
#define AROW 272
#define BROW 272
#define SB_H 1024
#define SB_L (SB_H + 256 * BROW)
#define SA_H (SB_L + 256 * BROW)
#define SA_L (SA_H + 128 * AROW)
#define SMEM_P (SA_L + 128 * AROW)

__device__ __forceinline__ uint32_t smem_u32(const void* p) {
    uint32_t a;
    asm("{ .reg .u64 t; cvta.to.shared.u64 t, %1; cvt.u32.u64 %0, t; }"
        : "=r"(a) : "l"(p));
    return a;
}
__device__ __forceinline__ void mma16816f(float* d, const uint32_t* a,
                                          uint32_t b0, uint32_t b1) {
    asm volatile(
        "mma.sync.aligned.m16n8k16.row.col.f32.f16.f16.f32 "
        "{%0,%1,%2,%3}, {%4,%5,%6,%7}, {%8,%9}, {%0,%1,%2,%3};"
        : "+f"(d[0]), "+f"(d[1]), "+f"(d[2]), "+f"(d[3])
        : "r"(a[0]), "r"(a[1]), "r"(a[2]), "r"(a[3]), "r"(b0), "r"(b1));
}
#define LDSM_X4(r0, r1, r2, r3, addr)                                        \
    asm volatile("ldmatrix.sync.aligned.m8n8.x4.shared.b16 {%0,%1,%2,%3}, [%4];" \
                 : "=r"(r0), "=r"(r1), "=r"(r2), "=r"(r3) : "r"(addr))

__device__ __forceinline__ void stage_B(char* sm, const uint4* BhG, const uint4* BlG,
                                        int tid) {
    for (int idx = tid; idx < 4096; idx += 256) {
        int o = idx >> 4, c = idx & 15;
        *(uint4*)(sm + SB_H + o * BROW + c * 16) = BhG[idx];
        *(uint4*)(sm + SB_L + o * BROW + c * 16) = BlG[idx];
    }
}

// NP=3: acc = Ah*(Bh+Bl) + Al*Bh   [layer 1: A = x split hi/lo at SA_H/SA_L]
// NP=2: acc = A*(Bh+Bl)            [layers 2/3: A fp16 exact, at a_base]
// A fragments loaded ONCE per k16, reused across B-hi and B-lo.
template <int NP>
__device__ __forceinline__ void mma_and_epilogue(
    uint32_t smb, int nbase, int wid, int lane,
    const float* sbias, uint4* Z, uint4* Y, uint32_t a_base) {
    int g = lane >> 2;
    int t4 = lane & 3;
    int wm = wid & 3;
    int wn = wid >> 2;
    uint32_t a_off0 = (uint32_t)((wm * 32 + (lane & 15)) * AROW + ((lane >> 4) * 8) * 2);
    uint32_t a_off1 = a_off0 + 16 * AROW;
    uint32_t b_off = (uint32_t)((wn * 128 + (lane & 7) + ((lane & 16) ? 8 : 0)) * BROW +
                                ((lane & 8) ? 16 : 0));
    float acc[2][16][4];
#pragma unroll
    for (int mt = 0; mt < 2; mt++)
#pragma unroll
        for (int n8 = 0; n8 < 16; n8++)
#pragma unroll
            for (int q = 0; q < 4; q++) acc[mt][n8][q] = 0.f;

#pragma unroll
    for (int k16 = 0; k16 < 8; k16++) {
        uint32_t ka = (uint32_t)(k16 * 32);
        uint32_t ah[2][4], al[2][4];
        LDSM_X4(ah[0][0], ah[0][1], ah[0][2], ah[0][3], smb + a_base + a_off0 + ka);
        LDSM_X4(ah[1][0], ah[1][1], ah[1][2], ah[1][3], smb + a_base + a_off1 + ka);
        if (NP == 3) {
            LDSM_X4(al[0][0], al[0][1], al[0][2], al[0][3], smb + SA_L + a_off0 + ka);
            LDSM_X4(al[1][0], al[1][1], al[1][2], al[1][3], smb + SA_L + a_off1 + ka);
        }
#pragma unroll
        for (int p = 0; p < 8; p++) {
            uint32_t b0, b1, b2, b3;
            uint32_t bpo = b_off + (uint32_t)(p * 16 * BROW) + ka;
            LDSM_X4(b0, b1, b2, b3, smb + SB_H + bpo);
            mma16816f(acc[0][2 * p], ah[0], b0, b1);
            mma16816f(acc[0][2 * p + 1], ah[0], b2, b3);
            mma16816f(acc[1][2 * p], ah[1], b0, b1);
            mma16816f(acc[1][2 * p + 1], ah[1], b2, b3);
            if (NP == 3) {
                mma16816f(acc[0][2 * p], al[0], b0, b1);
                mma16816f(acc[0][2 * p + 1], al[0], b2, b3);
                mma16816f(acc[1][2 * p], al[1], b0, b1);
                mma16816f(acc[1][2 * p + 1], al[1], b2, b3);
            }
            LDSM_X4(b0, b1, b2, b3, smb + SB_L + bpo);
            mma16816f(acc[0][2 * p], ah[0], b0, b1);
            mma16816f(acc[0][2 * p + 1], ah[0], b2, b3);
            mma16816f(acc[1][2 * p], ah[1], b0, b1);
            mma16816f(acc[1][2 * p + 1], ah[1], b2, b3);
        }
    }

    __half2* Zh = (__half2*)Z;
    __half2* Yh = (__half2*)Y;
#pragma unroll
    for (int mt = 0; mt < 2; mt++) {
        int r0 = wm * 32 + mt * 16 + g;
        int gn0 = nbase + r0;
        int gn1 = gn0 + 8;
#pragma unroll
        for (int n8 = 0; n8 < 16; n8++) {
            int col = n8 * 8 + t4 * 2;
            if (wn == 0) {
                if (gn0 < N_NODES)
                    Zh[gn0 * 64 + (col >> 1)] =
                        __floats2half2_rn(acc[mt][n8][0], acc[mt][n8][1]);
                if (gn1 < N_NODES)
                    Zh[gn1 * 64 + (col >> 1)] =
                        __floats2half2_rn(acc[mt][n8][2], acc[mt][n8][3]);
            } else {
                float b0v = sbias[col], b1v = sbias[col + 1];
                if (gn0 < N_NODES)
                    Yh[gn0 * 64 + (col >> 1)] =
                        __floats2half2_rn(acc[mt][n8][0] + b0v, acc[mt][n8][1] + b1v);
                if (gn1 < N_NODES)
                    Yh[gn1 * 64 + (col >> 1)] =
                        __floats2half2_rn(acc[mt][n8][2] + b0v, acc[mt][n8][3] + b1v);
            }
        }
    }
}

// ---------------- layer-1 projection: fp32 x, A split fp16 hi/lo (3 passes) ----------
__global__ void __launch_bounds__(256, 1) k_projA(
    const float* __restrict__ x, const uint4* __restrict__ BhG,
    const uint4* __restrict__ BlG, const float* __restrict__ bias,
    uint4* __restrict__ Z, uint4* __restrict__ Y) {
    extern __shared__ char sm[];
    uint32_t smb = smem_u32(sm);
    int tid = threadIdx.x;
    int wid = tid >> 5;
    int lane = tid & 31;
    float* sbias = (float*)(sm + 512);
    if (tid < HID) sbias[tid] = bias[tid];
    stage_B(sm, BhG, BlG, tid);

    for (int tile = blockIdx.x; tile < NTILES128; tile += gridDim.x) {
        int nbase = tile * 128;
        __syncthreads();
        for (int idx = tid; idx < 8192; idx += 256) {
            int row = idx >> 6, ip = idx & 63;
            int gn = nbase + row;
            float2 v = make_float2(0.f, 0.f);
            if (gn < N_NODES) v = ((const float2*)x)[gn * 64 + ip];
            __half h0 = __float2half_rn(v.x), h1 = __float2half_rn(v.y);
            __half l0 = __float2half_rn(v.x - __half2float(h0));
            __half l1 = __float2half_rn(v.y - __half2float(h1));
            uint32_t off = (uint32_t)(row * AROW + ip * 4);
            *(__half2*)(sm + SA_H + off) = __halves2half2(h0, h1);
            *(__half2*)(sm + SA_L + off) = __halves2half2(l0, l1);
        }
        __syncthreads();
        mma_and_epilogue<3>(smb, nbase, wid, lane, sbias, Z, Y, SA_H);
    }
}

// ---------------- layers 2/3: fp16 h input, exact A, 2 passes, double-buffered A ----
__global__ void __launch_bounds__(256, 1) k_projH(
    const uint4* __restrict__ h, const uint4* __restrict__ BhG,
    const uint4* __restrict__ BlG, const float* __restrict__ bias,
    uint4* __restrict__ Z, uint4* __restrict__ Y) {
    extern __shared__ char sm[];
    uint32_t smb = smem_u32(sm);
    int tid = threadIdx.x;
    int wid = tid >> 5;
    int lane = tid & 31;
    float* sbias = (float*)(sm + 512);
    if (tid < HID) sbias[tid] = bias[tid];
    stage_B(sm, BhG, BlG, tid);

    // A staging indexing: thread handles 8 uint4 (rows tid>>4 stepped by 16)
    int c0 = tid & 15;
    int r0 = tid >> 4;

    // prologue: stage first tile into buf0 (SA_H)
    int tile = blockIdx.x;
    if (tile < NTILES128) {
        int nbase = tile * 128;
#pragma unroll
        for (int q = 0; q < 8; q++) {
            int row = r0 + q * 16;
            int gn = nbase + row;
            uint4 v = make_uint4(0, 0, 0, 0);
            if (gn < N_NODES) v = h[gn * 16 + c0];
            *(uint4*)(sm + SA_H + row * AROW + c0 * 16) = v;
        }
    }
    __syncthreads();

    int buf = 0;
    for (; tile < NTILES128; tile += gridDim.x) {
        int nbase = tile * 128;
        int next = tile + gridDim.x;
        bool has_next = next < NTILES128;
        uint4 v[8];
        if (has_next) {
            int nb = next * 128;
#pragma unroll
            for (int q = 0; q < 8; q++) {
                int row = r0 + q * 16;
                int gn = nb + row;
                v[q] = make_uint4(0, 0, 0, 0);
                if (gn < N_NODES) v[q] = h[gn * 16 + c0];
            }
        }
        mma_and_epilogue<2>(smb, nbase, wid, lane, sbias, Z, Y,
                            buf ? (uint32_t)SA_L : (uint32_t)SA_H);
        if (has_next) {
            uint32_t ob = buf ? (uint32_t)SA_H : (uint32_t)SA_L;
#pragma unroll
            for (int q = 0; q < 8; q++) {
                int row = r0 + q * 16;
                *(uint4*)(sm + ob + row * AROW + c0 * 16) = v[q];
            }
        }
        __syncthreads();
        buf ^= 1;
    }
}

// ---------------- aggregation: out = relu?(S@Z + Y), 8-edge pipelined gather --------
#define ACCUM8(vv)                                                            \
    do {                                                                      \
        _Pragma("unroll") for (int p = 0; p < 8; p++) {                       \
            _Pragma("unroll") for (int q = 0; q < 4; q++) {                   \
                uint32_t u = (&(vv)[p].x)[q];                                 \
                float2 f = __half22float2(*(__half2*)&u);                     \
                acc[2 * q] += f.x;                                            \
                acc[2 * q + 1] += f.y;                                        \
            }                                                                 \
        }                                                                     \
    } while (0)

__global__ void k_agg(const uint4* __restrict__ Z, const uint4* __restrict__ Y,
                      __half2* __restrict__ out, int do_relu) {
    int w = (blockIdx.x * blockDim.x + threadIdx.x) >> 5;
    int lane = threadIdx.x & 31;
    int node = w * 2 + (lane >> 4);
    int l16 = lane & 15;
    if (node >= N_NODES) return;
    int s = g_off[node];
    int e = g_off[node + 1];
    float acc[8];
#pragma unroll
    for (int q = 0; q < 8; q++) acc[q] = 0.f;

    int j = s;
    if (j + 8 <= e) {
        uint4 v[8];
        {
            int id[8];
#pragma unroll
            for (int q = 0; q < 8; q++) id[q] = __ldg(&g_ssrc[j + q]);
#pragma unroll
            for (int q = 0; q < 8; q++) v[q] = Z[id[q] * 16 + l16];
            j += 8;
        }
        while (j + 8 <= e) {
            int nid[8];
#pragma unroll
            for (int q = 0; q < 8; q++) nid[q] = __ldg(&g_ssrc[j + q]);
            j += 8;
            ACCUM8(v);
#pragma unroll
            for (int q = 0; q < 8; q++) v[q] = Z[nid[q] * 16 + l16];
        }
        ACCUM8(v);
    }
    for (; j < e; j++) {
        int s0 = __ldg(&g_ssrc[j]);
        uint4 v0 = Z[s0 * 16 + l16];
#pragma unroll
        for (int q = 0; q < 4; q++) {
            uint32_t u0 = (&v0.x)[q];
            float2 f0 = __half22float2(*(__half2*)&u0);
            acc[2 * q] += f0.x;
            acc[2 * q + 1] += f0.y;
        }
    }

    uint4 yv = Y[node * 16 + l16];
#pragma unroll
    for (int q = 0; q < 4; q++) {
        uint32_t u = (&yv.x)[q];
        float2 f = __half22float2(*(__half2*)&u);
        float rx = acc[2 * q] + f.x;
        float ry = acc[2 * q + 1] + f.y;
        if (do_relu) { rx = fmaxf(rx, 0.f); ry = fmaxf(ry, 0.f); }
        out[node * 64 + l16 * 4 + q] = __floats2half2_rn(rx, ry);
    }
}

// ---------------- pooling (fp16 input) ----------------
__global__ void k_pool(const __half* __restrict__ h, const int* __restrict__ batch) {
    int base = blockIdx.x * 32;
    int col = threadIdx.x;
    int end = base + 32;
    if (end > N_NODES) end = N_NODES;
    if (base >= N_NODES) return;
    int cur = batch[base];
    float sum = 0.f;
    for (int n = base; n < end; n++) {
        int b = batch[n];
        if (b != cur) {
            atomicAdd(&g_pool[cur * HID + col], sum);
            sum = 0.f;
            cur = b;
        }
        sum += __half2float(h[n * HID + col]);
    }
    atomicAdd(&g_pool[cur * HID + col], sum);
}

// ---------------- output head ----------------
__global__ void k_out(const float* __restrict__ Wout, const float* __restrict__ bout,
                      float* __restrict__ out) {
    int t = threadIdx.x;
    if (t < NGRAPH * NCLASS) {
        int g = t / NCLASS;
        int c = t % NCLASS;
        float s = bout[c];
#pragma unroll 4
        for (int k = 0; k < HID; k++) s += g_pool[g * HID + k] * Wout[c * HID + k];
        out[t] = s;
    }
}

// ---------------- launch ----------------
extern "C" void kernel_launch(void* const* d_in, const int* in_sizes, int n_in,
                              void* d_out, int out_size) {
    const float* x = (const float*)d_in[0];
    const int* ei = (const int*)d_in[1];
    const int* src = ei;
    const int* dst = ei + N_EDGES;
    const int* batch = (const int*)d_in[2];
    const float* W1l = (const float*)d_in[3];
    const float* b1 = (const float*)d_in[4];
    const float* W1r = (const float*)d_in[5];
    const float* W2l = (const float*)d_in[6];
    const float* b2 = (const float*)d_in[7];
    const float* W2r = (const float*)d_in[8];
    const float* W3l = (const float*)d_in[9];
    const float* b3 = (const float*)d_in[10];
    const float* W3r = (const float*)d_in[11];
    const float* Wout = (const float*)d_in[12];
    const float* bout = (const float*)d_in[13];
    float* out = (float*)d_out;

    cudaFuncSetAttribute(k_projA, cudaFuncAttributeMaxDynamicSharedMemorySize, SMEM_P);
    cudaFuncSetAttribute(k_projH, cudaFuncAttributeMaxDynamicSharedMemorySize, SMEM_P);

    uint4* d_Z; cudaGetSymbolAddress((void**)&d_Z, g_Z);
    uint4* d_Y; cudaGetSymbolAddress((void**)&d_Y, g_Y);
    uint4* d_h; cudaGetSymbolAddress((void**)&d_h, g_h);
    uint4* d_Bh; cudaGetSymbolAddress((void**)&d_Bh, g_Bh);
    uint4* d_Bl; cudaGetSymbolAddress((void**)&d_Bl, g_Bl);

    // prep (zero + weight split) then CSR build
    k_prep<<<(N_NODES + 255) / 256, 256>>>(W1l, W1r, W2l, W2r, W3l, W3r,
                                           (__half*)d_Bh, (__half*)d_Bl);
    k_hist<<<(N_EDGES + 255) / 256, 256>>>(dst);
    k_scan1<<<SCAN_NB, 1024>>>();
    k_scan2<<<1, 1024>>>();
    k_scan3<<<(N_NODES + 255) / 256, 256>>>();
    k_scatter<<<(N_EDGES + 255) / 256, 256>>>(src, dst);

    // layer 1: x -> Z,Y -> h (relu)
    k_projA<<<PROJ_GRID, 256, SMEM_P>>>(x, d_Bh, d_Bl, b1, d_Z, d_Y);
    k_agg<<<(N_NODES / 2 + 7) / 8, 256>>>(d_Z, d_Y, (__half2*)d_h, 1);
    // layer 2
    k_projH<<<PROJ_GRID, 256, SMEM_P>>>(d_h, d_Bh + 4096, d_Bl + 4096, b2, d_Z, d_Y);
    k_agg<<<(N_NODES / 2 + 7) / 8, 256>>>(d_Z, d_Y, (__half2*)d_h, 1);
    // layer 3 (no relu)
    k_projH<<<PROJ_GRID, 256, SMEM_P>>>(d_h, d_Bh + 8192, d_Bl + 8192, b3, d_Z, d_Y);
    k_agg<<<(N_NODES / 2 + 7) / 8, 256>>>(d_Z, d_Y, (__half2*)d_h, 0);

    // pooling + head
    k_pool<<<(N_NODES + 31) / 32, 128>>>((const __half*)d_h, batch);
    k_out<<<1, 640>>>(Wout, bout, out);
}

// round 15
// speedup vs baseline: 1.0493x; 1.0493x over previous
#include <cuda_runtime.h>
#include <cuda_fp16.h>
#include <cstdint>

#define N_NODES 100000
#define N_EDGES 1600000
#define HID 128
#define NGRAPH 64
#define NCLASS 10
#define SCAN_NB ((N_NODES + 1023) / 1024)
#define NTILES128 ((N_NODES + 127) / 128)
#define PROJ_GRID 148

// ---------------- scratch (no allocations allowed) ----------------
__device__ uint4  g_Z[N_NODES * 16];      // h@Wl^T, fp16
__device__ uint4  g_Y[N_NODES * 16];      // h@Wr^T + b, fp16
__device__ uint4  g_h[N_NODES * 16];      // layer intermediate h, fp16
__device__ uint4  g_Bh[3 * 4096];         // per-layer [Wl;Wr] fp16 hi
__device__ uint4  g_Bl[3 * 4096];         // per-layer fp16 lo
__device__ int    g_cnt[N_NODES];
__device__ int    g_off[N_NODES + 1];
__device__ int    g_ssrc[N_EDGES];
__device__ int    g_bsum[1024];
__device__ float  g_pool[NGRAPH * HID];

// ---------------- prep: zero cnt/pool + weight fp16 hi/lo split (one launch) --------
__global__ void k_prep(const float* __restrict__ W1l, const float* __restrict__ W1r,
                       const float* __restrict__ W2l, const float* __restrict__ W2r,
                       const float* __restrict__ W3l, const float* __restrict__ W3r,
                       __half* __restrict__ Bh, __half* __restrict__ Bl) {
    int idx = blockIdx.x * blockDim.x + threadIdx.x;
    if (idx < N_NODES) g_cnt[idx] = 0;
    if (idx < NGRAPH * HID) g_pool[idx] = 0.0f;
    if (idx < 3 * 32768) {
        int layer = idx >> 15;
        int r = idx & 32767;
        int o = r >> 7, k = r & 127;
        const float* W = (layer == 0) ? ((o < 128) ? W1l : W1r)
                       : (layer == 1) ? ((o < 128) ? W2l : W2r)
                                      : ((o < 128) ? W3l : W3r);
        float f = W[(o & 127) * 128 + k];
        __half h = __float2half_rn(f);
        Bh[idx] = h;
        Bl[idx] = __float2half_rn(f - __half2float(h));
    }
}

// ---------------- CSR build ----------------
__global__ void k_hist(const int* __restrict__ dst) {
    int e = blockIdx.x * blockDim.x + threadIdx.x;
    if (e < N_EDGES) atomicAdd(&g_cnt[dst[e]], 1);
}
__global__ void k_scan1() {
    __shared__ int sh[1024];
    int t = threadIdx.x;
    int i = blockIdx.x * 1024 + t;
    int v = (i < N_NODES) ? g_cnt[i] : 0;
    sh[t] = v;
    __syncthreads();
    for (int d = 1; d < 1024; d <<= 1) {
        int tv = (t >= d) ? sh[t - d] : 0;
        __syncthreads();
        sh[t] += tv;
        __syncthreads();
    }
    if (i < N_NODES) g_off[i] = sh[t] - v;
    if (t == 1023) g_bsum[blockIdx.x] = sh[1023];
}
__global__ void k_scan2() {
    __shared__ int sh[1024];
    int t = threadIdx.x;
    int v = (t < SCAN_NB) ? g_bsum[t] : 0;
    sh[t] = v;
    __syncthreads();
    for (int d = 1; d < 1024; d <<= 1) {
        int tv = (t >= d) ? sh[t - d] : 0;
        __syncthreads();
        sh[t] += tv;
        __syncthreads();
    }
    if (t < SCAN_NB) g_bsum[t] = sh[t] - v;
}
__global__ void k_scan3() {
    int i = blockIdx.x * blockDim.x + threadIdx.x;
    if (i < N_NODES) {
        int o = g_off[i] + g_bsum[i >> 10];
        g_off[i] = o;
        g_cnt[i] = o;
    }
    if (i == 0) g_off[N_NODES] = N_EDGES;
}
__global__ void k_scatter(const int* __restrict__ src, const int* __restrict__ dst) {
    int e = blockIdx.x * blockDim.x + threadIdx.x;
    if (e < N_EDGES) {
        int d = dst[e];
        int pos = atomicAdd(&g_cnt[d], 1);
        g_ssrc[pos] = src[e];
    }
}

// ---------------- GEMM machinery ----------------
#define AROW 272
#define BROW 272
#define SB_H 1024
#define SB_L (SB_H + 256 * BROW)
#define SA_H (SB_L + 256 * BROW)
#define SA_L (SA_H + 128 * AROW)
#define SMEM_P (SA_L + 128 * AROW)

__device__ __forceinline__ uint32_t smem_u32(const void* p) {
    uint32_t a;
    asm("{ .reg .u64 t; cvta.to.shared.u64 t, %1; cvt.u32.u64 %0, t; }"
        : "=r"(a) : "l"(p));
    return a;
}
__device__ __forceinline__ void mma16816f(float* d, const uint32_t* a,
                                          uint32_t b0, uint32_t b1) {
    asm volatile(
        "mma.sync.aligned.m16n8k16.row.col.f32.f16.f16.f32 "
        "{%0,%1,%2,%3}, {%4,%5,%6,%7}, {%8,%9}, {%0,%1,%2,%3};"
        : "+f"(d[0]), "+f"(d[1]), "+f"(d[2]), "+f"(d[3])
        : "r"(a[0]), "r"(a[1]), "r"(a[2]), "r"(a[3]), "r"(b0), "r"(b1));
}
#define LDSM_X4(r0, r1, r2, r3, addr)                                        \
    asm volatile("ldmatrix.sync.aligned.m8n8.x4.shared.b16 {%0,%1,%2,%3}, [%4];" \
                 : "=r"(r0), "=r"(r1), "=r"(r2), "=r"(r3) : "r"(addr))

__device__ __forceinline__ void stage_B(char* sm, const uint4* BhG, const uint4* BlG,
                                        int tid) {
    for (int idx = tid; idx < 4096; idx += 256) {
        int o = idx >> 4, c = idx & 15;
        *(uint4*)(sm + SB_H + o * BROW + c * 16) = BhG[idx];
        *(uint4*)(sm + SB_L + o * BROW + c * 16) = BlG[idx];
    }
}

// NP=3: acc = Ah*(Bh+Bl) + Al*Bh   [layer 1: A = x split hi/lo]
// NP=2: acc = A*(Bh+Bl)            [layers 2/3: A fp16 exact]
// A fragments loaded ONCE per k16 and reused for both B passes.
template <int NP>
__device__ __forceinline__ void mma_and_epilogue(
    uint32_t smb, int nbase, int wid, int lane,
    const float* sbias, uint4* Z, uint4* Y) {
    int g = lane >> 2;
    int t4 = lane & 3;
    int wm = wid & 3;
    int wn = wid >> 2;
    uint32_t a_off0 = (uint32_t)((wm * 32 + (lane & 15)) * AROW + ((lane >> 4) * 8) * 2);
    uint32_t a_off1 = a_off0 + 16 * AROW;
    uint32_t b_off = (uint32_t)((wn * 128 + (lane & 7) + ((lane & 16) ? 8 : 0)) * BROW +
                                ((lane & 8) ? 16 : 0));
    float acc[2][16][4];
#pragma unroll
    for (int mt = 0; mt < 2; mt++)
#pragma unroll
        for (int n8 = 0; n8 < 16; n8++)
#pragma unroll
            for (int q = 0; q < 4; q++) acc[mt][n8][q] = 0.f;

#pragma unroll
    for (int k16 = 0; k16 < 8; k16++) {
        uint32_t ka = (uint32_t)(k16 * 32);
        uint32_t ah[2][4], al[2][4];
        LDSM_X4(ah[0][0], ah[0][1], ah[0][2], ah[0][3], smb + SA_H + a_off0 + ka);
        LDSM_X4(ah[1][0], ah[1][1], ah[1][2], ah[1][3], smb + SA_H + a_off1 + ka);
        if (NP == 3) {
            LDSM_X4(al[0][0], al[0][1], al[0][2], al[0][3], smb + SA_L + a_off0 + ka);
            LDSM_X4(al[1][0], al[1][1], al[1][2], al[1][3], smb + SA_L + a_off1 + ka);
        }
#pragma unroll
        for (int p = 0; p < 8; p++) {
            uint32_t b0, b1, b2, b3;
            uint32_t bpo = b_off + (uint32_t)(p * 16 * BROW) + ka;
            LDSM_X4(b0, b1, b2, b3, smb + SB_H + bpo);
            mma16816f(acc[0][2 * p], ah[0], b0, b1);
            mma16816f(acc[0][2 * p + 1], ah[0], b2, b3);
            mma16816f(acc[1][2 * p], ah[1], b0, b1);
            mma16816f(acc[1][2 * p + 1], ah[1], b2, b3);
            if (NP == 3) {
                mma16816f(acc[0][2 * p], al[0], b0, b1);
                mma16816f(acc[0][2 * p + 1], al[0], b2, b3);
                mma16816f(acc[1][2 * p], al[1], b0, b1);
                mma16816f(acc[1][2 * p + 1], al[1], b2, b3);
            }
            LDSM_X4(b0, b1, b2, b3, smb + SB_L + bpo);
            mma16816f(acc[0][2 * p], ah[0], b0, b1);
            mma16816f(acc[0][2 * p + 1], ah[0], b2, b3);
            mma16816f(acc[1][2 * p], ah[1], b0, b1);
            mma16816f(acc[1][2 * p + 1], ah[1], b2, b3);
        }
    }

    __half2* Zh = (__half2*)Z;
    __half2* Yh = (__half2*)Y;
#pragma unroll
    for (int mt = 0; mt < 2; mt++) {
        int r0 = wm * 32 + mt * 16 + g;
        int gn0 = nbase + r0;
        int gn1 = gn0 + 8;
#pragma unroll
        for (int n8 = 0; n8 < 16; n8++) {
            int col = n8 * 8 + t4 * 2;
            if (wn == 0) {
                if (gn0 < N_NODES)
                    Zh[gn0 * 64 + (col >> 1)] =
                        __floats2half2_rn(acc[mt][n8][0], acc[mt][n8][1]);
                if (gn1 < N_NODES)
                    Zh[gn1 * 64 + (col >> 1)] =
                        __floats2half2_rn(acc[mt][n8][2], acc[mt][n8][3]);
            } else {
                float b0v = sbias[col], b1v = sbias[col + 1];
                if (gn0 < N_NODES)
                    Yh[gn0 * 64 + (col >> 1)] =
                        __floats2half2_rn(acc[mt][n8][0] + b0v, acc[mt][n8][1] + b1v);
                if (gn1 < N_NODES)
                    Yh[gn1 * 64 + (col >> 1)] =
                        __floats2half2_rn(acc[mt][n8][2] + b0v, acc[mt][n8][3] + b1v);
            }
        }
    }
}

// ---------------- layer-1 projection: fp32 x, A split fp16 hi/lo (3 passes) ----------
__global__ void __launch_bounds__(256, 1) k_projA(
    const float* __restrict__ x, const uint4* __restrict__ BhG,
    const uint4* __restrict__ BlG, const float* __restrict__ bias,
    uint4* __restrict__ Z, uint4* __restrict__ Y) {
    extern __shared__ char sm[];
    uint32_t smb = smem_u32(sm);
    int tid = threadIdx.x;
    int wid = tid >> 5;
    int lane = tid & 31;
    float* sbias = (float*)(sm + 512);
    if (tid < HID) sbias[tid] = bias[tid];
    stage_B(sm, BhG, BlG, tid);

    for (int tile = blockIdx.x; tile < NTILES128; tile += gridDim.x) {
        int nbase = tile * 128;
        __syncthreads();
        for (int idx = tid; idx < 8192; idx += 256) {
            int row = idx >> 6, ip = idx & 63;
            int gn = nbase + row;
            float2 v = make_float2(0.f, 0.f);
            if (gn < N_NODES) v = ((const float2*)x)[gn * 64 + ip];
            __half h0 = __float2half_rn(v.x), h1 = __float2half_rn(v.y);
            __half l0 = __float2half_rn(v.x - __half2float(h0));
            __half l1 = __float2half_rn(v.y - __half2float(h1));
            uint32_t off = (uint32_t)(row * AROW + ip * 4);
            *(__half2*)(sm + SA_H + off) = __halves2half2(h0, h1);
            *(__half2*)(sm + SA_L + off) = __halves2half2(l0, l1);
        }
        __syncthreads();
        mma_and_epilogue<3>(smb, nbase, wid, lane, sbias, Z, Y);
    }
}

// ---------------- layers 2/3 projection: fp16 h input (exact A, 2 passes) ----------
__global__ void __launch_bounds__(256, 1) k_projH(
    const uint4* __restrict__ h, const uint4* __restrict__ BhG,
    const uint4* __restrict__ BlG, const float* __restrict__ bias,
    uint4* __restrict__ Z, uint4* __restrict__ Y) {
    extern __shared__ char sm[];
    uint32_t smb = smem_u32(sm);
    int tid = threadIdx.x;
    int wid = tid >> 5;
    int lane = tid & 31;
    float* sbias = (float*)(sm + 512);
    if (tid < HID) sbias[tid] = bias[tid];
    stage_B(sm, BhG, BlG, tid);

    for (int tile = blockIdx.x; tile < NTILES128; tile += gridDim.x) {
        int nbase = tile * 128;
        __syncthreads();
        for (int idx = tid; idx < 2048; idx += 256) {
            int row = idx >> 4, c = idx & 15;
            int gn = nbase + row;
            uint4 v = make_uint4(0, 0, 0, 0);
            if (gn < N_NODES) v = h[gn * 16 + c];
            *(uint4*)(sm + SA_H + row * AROW + c * 16) = v;
        }
        __syncthreads();
        mma_and_epilogue<2>(smb, nbase, wid, lane, sbias, Z, Y);
    }
}

// ---------------- aggregation: out = relu?(S@Z + Y), fp16 out, 2 nodes/warp ----------
__global__ void k_agg(const uint4* __restrict__ Z, const uint4* __restrict__ Y,
                      __half2* __restrict__ out, int do_relu) {
    int w = (blockIdx.x * blockDim.x + threadIdx.x) >> 5;
    int lane = threadIdx.x & 31;
    int node = w * 2 + (lane >> 4);
    int l16 = lane & 15;
    if (node >= N_NODES) return;
    int s = g_off[node];
    int e = g_off[node + 1];
    float acc[8];
#pragma unroll
    for (int q = 0; q < 8; q++) acc[q] = 0.f;
    int j = s;
    for (; j + 3 < e; j += 4) {
        int s0 = __ldg(&g_ssrc[j]);
        int s1 = __ldg(&g_ssrc[j + 1]);
        int s2 = __ldg(&g_ssrc[j + 2]);
        int s3 = __ldg(&g_ssrc[j + 3]);
        uint4 v0 = Z[s0 * 16 + l16];
        uint4 v1 = Z[s1 * 16 + l16];
        uint4 v2 = Z[s2 * 16 + l16];
        uint4 v3 = Z[s3 * 16 + l16];
#pragma unroll
        for (int q = 0; q < 4; q++) {
            uint32_t u0 = (&v0.x)[q], u1 = (&v1.x)[q], u2 = (&v2.x)[q], u3 = (&v3.x)[q];
            float2 f0 = __half22float2(*(__half2*)&u0);
            float2 f1 = __half22float2(*(__half2*)&u1);
            float2 f2 = __half22float2(*(__half2*)&u2);
            float2 f3 = __half22float2(*(__half2*)&u3);
            acc[2 * q] += (f0.x + f1.x) + (f2.x + f3.x);
            acc[2 * q + 1] += (f0.y + f1.y) + (f2.y + f3.y);
        }
    }
    for (; j < e; j++) {
        int s0 = __ldg(&g_ssrc[j]);
        uint4 v0 = Z[s0 * 16 + l16];
#pragma unroll
        for (int q = 0; q < 4; q++) {
            uint32_t u0 = (&v0.x)[q];
            float2 f0 = __half22float2(*(__half2*)&u0);
            acc[2 * q] += f0.x;
            acc[2 * q + 1] += f0.y;
        }
    }
    uint4 yv = Y[node * 16 + l16];
#pragma unroll
    for (int q = 0; q < 4; q++) {
        uint32_t u = (&yv.x)[q];
        float2 f = __half22float2(*(__half2*)&u);
        float rx = acc[2 * q] + f.x;
        float ry = acc[2 * q + 1] + f.y;
        if (do_relu) { rx = fmaxf(rx, 0.f); ry = fmaxf(ry, 0.f); }
        out[node * 64 + l16 * 4 + q] = __floats2half2_rn(rx, ry);
    }
}

// ---------------- pooling (fp16 input) ----------------
__global__ void k_pool(const __half* __restrict__ h, const int* __restrict__ batch) {
    int base = blockIdx.x * 32;
    int col = threadIdx.x;
    int end = base + 32;
    if (end > N_NODES) end = N_NODES;
    if (base >= N_NODES) return;
    int cur = batch[base];
    float sum = 0.f;
    for (int n = base; n < end; n++) {
        int b = batch[n];
        if (b != cur) {
            atomicAdd(&g_pool[cur * HID + col], sum);
            sum = 0.f;
            cur = b;
        }
        sum += __half2float(h[n * HID + col]);
    }
    atomicAdd(&g_pool[cur * HID + col], sum);
}

// ---------------- output head ----------------
__global__ void k_out(const float* __restrict__ Wout, const float* __restrict__ bout,
                      float* __restrict__ out) {
    int t = threadIdx.x;
    if (t < NGRAPH * NCLASS) {
        int g = t / NCLASS;
        int c = t % NCLASS;
        float s = bout[c];
#pragma unroll 4
        for (int k = 0; k < HID; k++) s += g_pool[g * HID + k] * Wout[c * HID + k];
        out[t] = s;
    }
}

// ---------------- launch ----------------
extern "C" void kernel_launch(void* const* d_in, const int* in_sizes, int n_in,
                              void* d_out, int out_size) {
    const float* x = (const float*)d_in[0];
    const int* ei = (const int*)d_in[1];
    const int* src = ei;
    const int* dst = ei + N_EDGES;
    const int* batch = (const int*)d_in[2];
    const float* W1l = (const float*)d_in[3];
    const float* b1 = (const float*)d_in[4];
    const float* W1r = (const float*)d_in[5];
    const float* W2l = (const float*)d_in[6];
    const float* b2 = (const float*)d_in[7];
    const float* W2r = (const float*)d_in[8];
    const float* W3l = (const float*)d_in[9];
    const float* b3 = (const float*)d_in[10];
    const float* W3r = (const float*)d_in[11];
    const float* Wout = (const float*)d_in[12];
    const float* bout = (const float*)d_in[13];
    float* out = (float*)d_out;

    cudaFuncSetAttribute(k_projA, cudaFuncAttributeMaxDynamicSharedMemorySize, SMEM_P);
    cudaFuncSetAttribute(k_projH, cudaFuncAttributeMaxDynamicSharedMemorySize, SMEM_P);

    uint4* d_Z; cudaGetSymbolAddress((void**)&d_Z, g_Z);
    uint4* d_Y; cudaGetSymbolAddress((void**)&d_Y, g_Y);
    uint4* d_h; cudaGetSymbolAddress((void**)&d_h, g_h);
    uint4* d_Bh; cudaGetSymbolAddress((void**)&d_Bh, g_Bh);
    uint4* d_Bl; cudaGetSymbolAddress((void**)&d_Bl, g_Bl);

    // prep (zero + weight split) then CSR build
    k_prep<<<(N_NODES + 255) / 256, 256>>>(W1l, W1r, W2l, W2r, W3l, W3r,
                                           (__half*)d_Bh, (__half*)d_Bl);
    k_hist<<<(N_EDGES + 255) / 256, 256>>>(dst);
    k_scan1<<<SCAN_NB, 1024>>>();
    k_scan2<<<1, 1024>>>();
    k_scan3<<<(N_NODES + 255) / 256, 256>>>();
    k_scatter<<<(N_EDGES + 255) / 256, 256>>>(src, dst);

    // layer 1: x -> Z,Y -> h (relu)
    k_projA<<<PROJ_GRID, 256, SMEM_P>>>(x, d_Bh, d_Bl, b1, d_Z, d_Y);
    k_agg<<<(N_NODES / 2 + 7) / 8, 256>>>(d_Z, d_Y, (__half2*)d_h, 1);
    // layer 2
    k_projH<<<PROJ_GRID, 256, SMEM_P>>>(d_h, d_Bh + 4096, d_Bl + 4096, b2, d_Z, d_Y);
    k_agg<<<(N_NODES / 2 + 7) / 8, 256>>>(d_Z, d_Y, (__half2*)d_h, 1);
    // layer 3 (no relu)
    k_projH<<<PROJ_GRID, 256, SMEM_P>>>(d_h, d_Bh + 8192, d_Bl + 8192, b3, d_Z, d_Y);
    k_agg<<<(N_NODES / 2 + 7) / 8, 256>>>(d_Z, d_Y, (__half2*)d_h, 0);

    // pooling + head
    k_pool<<<(N_NODES + 31) / 32, 128>>>((const __half*)d_h, batch);
    k_out<<<1, 640>>>(Wout, bout, out);
}

// round 17
// speedup vs baseline: 1.1703x; 1.1154x over previous
#include <cuda_runtime.h>
#include <cuda_fp16.h>
#include <cstdint>

#define N_NODES 100000
#define N_EDGES 1600000
#define HID 128
#define NGRAPH 64
#define NCLASS 10
#define SCAN_NB ((N_NODES + 1023) / 1024)
#define NTILES128 ((N_NODES + 127) / 128)
#define PROJ_GRID 148

// ---------------- scratch (no allocations allowed) ----------------
__device__ uint4  g_Z[N_NODES * 16];      // h@Wl^T, fp16
__device__ uint4  g_Y[N_NODES * 16];      // h@Wr^T + b, fp16
__device__ uint4  g_h[N_NODES * 16];      // layer intermediate h, fp16
__device__ uint4  g_B[3 * 4096];          // per-layer [Wl;Wr] fp16 (rounded)
__device__ int    g_cnt[N_NODES];
__device__ int    g_off[N_NODES + 1];
__device__ int    g_ssrc[N_EDGES];
__device__ int    g_bsum[1024];
__device__ float  g_pool[NGRAPH * HID];

// ---------------- prep: zero cnt/pool + weight fp16 round (one launch) --------
__global__ void k_prep(const float* __restrict__ W1l, const float* __restrict__ W1r,
                       const float* __restrict__ W2l, const float* __restrict__ W2r,
                       const float* __restrict__ W3l, const float* __restrict__ W3r,
                       __half* __restrict__ B) {
    int idx = blockIdx.x * blockDim.x + threadIdx.x;
    if (idx < N_NODES) g_cnt[idx] = 0;
    if (idx < NGRAPH * HID) g_pool[idx] = 0.0f;
    if (idx < 3 * 32768) {
        int layer = idx >> 15;
        int r = idx & 32767;
        int o = r >> 7, k = r & 127;
        const float* W = (layer == 0) ? ((o < 128) ? W1l : W1r)
                       : (layer == 1) ? ((o < 128) ? W2l : W2r)
                                      : ((o < 128) ? W3l : W3r);
        B[idx] = __float2half_rn(W[(o & 127) * 128 + k]);
    }
}

// ---------------- CSR build ----------------
__global__ void k_hist(const int* __restrict__ dst) {
    int e = blockIdx.x * blockDim.x + threadIdx.x;
    if (e < N_EDGES) atomicAdd(&g_cnt[dst[e]], 1);
}
__global__ void k_scan1() {
    __shared__ int sh[1024];
    int t = threadIdx.x;
    int i = blockIdx.x * 1024 + t;
    int v = (i < N_NODES) ? g_cnt[i] : 0;
    sh[t] = v;
    __syncthreads();
    for (int d = 1; d < 1024; d <<= 1) {
        int tv = (t >= d) ? sh[t - d] : 0;
        __syncthreads();
        sh[t] += tv;
        __syncthreads();
    }
    if (i < N_NODES) g_off[i] = sh[t] - v;
    if (t == 1023) g_bsum[blockIdx.x] = sh[1023];
}
__global__ void k_scan2() {
    __shared__ int sh[1024];
    int t = threadIdx.x;
    int v = (t < SCAN_NB) ? g_bsum[t] : 0;
    sh[t] = v;
    __syncthreads();
    for (int d = 1; d < 1024; d <<= 1) {
        int tv = (t >= d) ? sh[t - d] : 0;
        __syncthreads();
        sh[t] += tv;
        __syncthreads();
    }
    if (t < SCAN_NB) g_bsum[t] = sh[t] - v;
}
__global__ void k_scan3() {
    int i = blockIdx.x * blockDim.x + threadIdx.x;
    if (i < N_NODES) {
        int o = g_off[i] + g_bsum[i >> 10];
        g_off[i] = o;
        g_cnt[i] = o;
    }
    if (i == 0) g_off[N_NODES] = N_EDGES;
}
__global__ void k_scatter(const int* __restrict__ src, const int* __restrict__ dst) {
    int e = blockIdx.x * blockDim.x + threadIdx.x;
    if (e < N_EDGES) {
        int d = dst[e];
        int pos = atomicAdd(&g_cnt[d], 1);
        g_ssrc[pos] = src[e];
    }
}

// ---------------- GEMM machinery ----------------
#define AROW 272
#define BROW 272
#define SB 1024
#define SA_H (SB + 256 * BROW)
#define SA_L (SA_H + 128 * AROW)
#define SMEM_P (SA_L + 128 * AROW)

__device__ __forceinline__ uint32_t smem_u32(const void* p) {
    uint32_t a;
    asm("{ .reg .u64 t; cvta.to.shared.u64 t, %1; cvt.u32.u64 %0, t; }"
        : "=r"(a) : "l"(p));
    return a;
}
__device__ __forceinline__ void mma16816f(float* d, const uint32_t* a,
                                          uint32_t b0, uint32_t b1) {
    asm volatile(
        "mma.sync.aligned.m16n8k16.row.col.f32.f16.f16.f32 "
        "{%0,%1,%2,%3}, {%4,%5,%6,%7}, {%8,%9}, {%0,%1,%2,%3};"
        : "+f"(d[0]), "+f"(d[1]), "+f"(d[2]), "+f"(d[3])
        : "r"(a[0]), "r"(a[1]), "r"(a[2]), "r"(a[3]), "r"(b0), "r"(b1));
}
#define LDSM_X4(r0, r1, r2, r3, addr)                                        \
    asm volatile("ldmatrix.sync.aligned.m8n8.x4.shared.b16 {%0,%1,%2,%3}, [%4];" \
                 : "=r"(r0), "=r"(r1), "=r"(r2), "=r"(r3) : "r"(addr))

__device__ __forceinline__ void stage_B(char* sm, const uint4* BG, int tid) {
    for (int idx = tid; idx < 4096; idx += 256) {
        int o = idx >> 4, c = idx & 15;
        *(uint4*)(sm + SB + o * BROW + c * 16) = BG[idx];
    }
}

// NA=2: acc = (Ah + Al) * B   [layer 1: A = x split hi/lo at SA_H/SA_L]
// NA=1: acc = A * B           [layers 2/3: A fp16 exact at SA_H]
// A fragments loaded once per k16.
template <int NA>
__device__ __forceinline__ void mma_and_epilogue(
    uint32_t smb, int nbase, int wid, int lane,
    const float* sbias, uint4* Z, uint4* Y) {
    int g = lane >> 2;
    int t4 = lane & 3;
    int wm = wid & 3;
    int wn = wid >> 2;
    uint32_t a_off0 = (uint32_t)((wm * 32 + (lane & 15)) * AROW + ((lane >> 4) * 8) * 2);
    uint32_t a_off1 = a_off0 + 16 * AROW;
    uint32_t b_off = (uint32_t)((wn * 128 + (lane & 7) + ((lane & 16) ? 8 : 0)) * BROW +
                                ((lane & 8) ? 16 : 0));
    float acc[2][16][4];
#pragma unroll
    for (int mt = 0; mt < 2; mt++)
#pragma unroll
        for (int n8 = 0; n8 < 16; n8++)
#pragma unroll
            for (int q = 0; q < 4; q++) acc[mt][n8][q] = 0.f;

#pragma unroll
    for (int k16 = 0; k16 < 8; k16++) {
        uint32_t ka = (uint32_t)(k16 * 32);
        uint32_t ah[2][4], al[2][4];
        LDSM_X4(ah[0][0], ah[0][1], ah[0][2], ah[0][3], smb + SA_H + a_off0 + ka);
        LDSM_X4(ah[1][0], ah[1][1], ah[1][2], ah[1][3], smb + SA_H + a_off1 + ka);
        if (NA == 2) {
            LDSM_X4(al[0][0], al[0][1], al[0][2], al[0][3], smb + SA_L + a_off0 + ka);
            LDSM_X4(al[1][0], al[1][1], al[1][2], al[1][3], smb + SA_L + a_off1 + ka);
        }
#pragma unroll
        for (int p = 0; p < 8; p++) {
            uint32_t b0, b1, b2, b3;
            LDSM_X4(b0, b1, b2, b3, smb + SB + b_off + (uint32_t)(p * 16 * BROW) + ka);
            mma16816f(acc[0][2 * p], ah[0], b0, b1);
            mma16816f(acc[0][2 * p + 1], ah[0], b2, b3);
            mma16816f(acc[1][2 * p], ah[1], b0, b1);
            mma16816f(acc[1][2 * p + 1], ah[1], b2, b3);
            if (NA == 2) {
                mma16816f(acc[0][2 * p], al[0], b0, b1);
                mma16816f(acc[0][2 * p + 1], al[0], b2, b3);
                mma16816f(acc[1][2 * p], al[1], b0, b1);
                mma16816f(acc[1][2 * p + 1], al[1], b2, b3);
            }
        }
    }

    __half2* Zh = (__half2*)Z;
    __half2* Yh = (__half2*)Y;
#pragma unroll
    for (int mt = 0; mt < 2; mt++) {
        int r0 = wm * 32 + mt * 16 + g;
        int gn0 = nbase + r0;
        int gn1 = gn0 + 8;
#pragma unroll
        for (int n8 = 0; n8 < 16; n8++) {
            int col = n8 * 8 + t4 * 2;
            if (wn == 0) {
                if (gn0 < N_NODES)
                    Zh[gn0 * 64 + (col >> 1)] =
                        __floats2half2_rn(acc[mt][n8][0], acc[mt][n8][1]);
                if (gn1 < N_NODES)
                    Zh[gn1 * 64 + (col >> 1)] =
                        __floats2half2_rn(acc[mt][n8][2], acc[mt][n8][3]);
            } else {
                float b0v = sbias[col], b1v = sbias[col + 1];
                if (gn0 < N_NODES)
                    Yh[gn0 * 64 + (col >> 1)] =
                        __floats2half2_rn(acc[mt][n8][0] + b0v, acc[mt][n8][1] + b1v);
                if (gn1 < N_NODES)
                    Yh[gn1 * 64 + (col >> 1)] =
                        __floats2half2_rn(acc[mt][n8][2] + b0v, acc[mt][n8][3] + b1v);
            }
        }
    }
}

// ---------------- layer-1 projection: fp32 x, A split fp16 hi/lo (2 passes) ----------
__global__ void __launch_bounds__(256, 1) k_projA(
    const float* __restrict__ x, const uint4* __restrict__ BG,
    const float* __restrict__ bias, uint4* __restrict__ Z, uint4* __restrict__ Y) {
    extern __shared__ char sm[];
    uint32_t smb = smem_u32(sm);
    int tid = threadIdx.x;
    int wid = tid >> 5;
    int lane = tid & 31;
    float* sbias = (float*)(sm + 512);
    if (tid < HID) sbias[tid] = bias[tid];
    stage_B(sm, BG, tid);

    for (int tile = blockIdx.x; tile < NTILES128; tile += gridDim.x) {
        int nbase = tile * 128;
        __syncthreads();
        for (int idx = tid; idx < 8192; idx += 256) {
            int row = idx >> 6, ip = idx & 63;
            int gn = nbase + row;
            float2 v = make_float2(0.f, 0.f);
            if (gn < N_NODES) v = ((const float2*)x)[gn * 64 + ip];
            __half h0 = __float2half_rn(v.x), h1 = __float2half_rn(v.y);
            __half l0 = __float2half_rn(v.x - __half2float(h0));
            __half l1 = __float2half_rn(v.y - __half2float(h1));
            uint32_t off = (uint32_t)(row * AROW + ip * 4);
            *(__half2*)(sm + SA_H + off) = __halves2half2(h0, h1);
            *(__half2*)(sm + SA_L + off) = __halves2half2(l0, l1);
        }
        __syncthreads();
        mma_and_epilogue<2>(smb, nbase, wid, lane, sbias, Z, Y);
    }
}

// ---------------- layers 2/3 projection: fp16 h input (exact A, 1 pass) ----------
__global__ void __launch_bounds__(256, 1) k_projH(
    const uint4* __restrict__ h, const uint4* __restrict__ BG,
    const float* __restrict__ bias, uint4* __restrict__ Z, uint4* __restrict__ Y) {
    extern __shared__ char sm[];
    uint32_t smb = smem_u32(sm);
    int tid = threadIdx.x;
    int wid = tid >> 5;
    int lane = tid & 31;
    float* sbias = (float*)(sm + 512);
    if (tid < HID) sbias[tid] = bias[tid];
    stage_B(sm, BG, tid);

    for (int tile = blockIdx.x; tile < NTILES128; tile += gridDim.x) {
        int nbase = tile * 128;
        __syncthreads();
        for (int idx = tid; idx < 2048; idx += 256) {
            int row = idx >> 4, c = idx & 15;
            int gn = nbase + row;
            uint4 v = make_uint4(0, 0, 0, 0);
            if (gn < N_NODES) v = h[gn * 16 + c];
            *(uint4*)(sm + SA_H + row * AROW + c * 16) = v;
        }
        __syncthreads();
        mma_and_epilogue<1>(smb, nbase, wid, lane, sbias, Z, Y);
    }
}

// ---------------- aggregation: out = relu?(S@Z + Y), fp16 out, 2 nodes/warp ----------
__global__ void k_agg(const uint4* __restrict__ Z, const uint4* __restrict__ Y,
                      __half2* __restrict__ out, int do_relu) {
    int w = (blockIdx.x * blockDim.x + threadIdx.x) >> 5;
    int lane = threadIdx.x & 31;
    int node = w * 2 + (lane >> 4);
    int l16 = lane & 15;
    if (node >= N_NODES) return;
    int s = g_off[node];
    int e = g_off[node + 1];
    float acc[8];
#pragma unroll
    for (int q = 0; q < 8; q++) acc[q] = 0.f;
    int j = s;
    for (; j + 3 < e; j += 4) {
        int s0 = __ldg(&g_ssrc[j]);
        int s1 = __ldg(&g_ssrc[j + 1]);
        int s2 = __ldg(&g_ssrc[j + 2]);
        int s3 = __ldg(&g_ssrc[j + 3]);
        uint4 v0 = Z[s0 * 16 + l16];
        uint4 v1 = Z[s1 * 16 + l16];
        uint4 v2 = Z[s2 * 16 + l16];
        uint4 v3 = Z[s3 * 16 + l16];
#pragma unroll
        for (int q = 0; q < 4; q++) {
            uint32_t u0 = (&v0.x)[q], u1 = (&v1.x)[q], u2 = (&v2.x)[q], u3 = (&v3.x)[q];
            float2 f0 = __half22float2(*(__half2*)&u0);
            float2 f1 = __half22float2(*(__half2*)&u1);
            float2 f2 = __half22float2(*(__half2*)&u2);
            float2 f3 = __half22float2(*(__half2*)&u3);
            acc[2 * q] += (f0.x + f1.x) + (f2.x + f3.x);
            acc[2 * q + 1] += (f0.y + f1.y) + (f2.y + f3.y);
        }
    }
    for (; j < e; j++) {
        int s0 = __ldg(&g_ssrc[j]);
        uint4 v0 = Z[s0 * 16 + l16];
#pragma unroll
        for (int q = 0; q < 4; q++) {
            uint32_t u0 = (&v0.x)[q];
            float2 f0 = __half22float2(*(__half2*)&u0);
            acc[2 * q] += f0.x;
            acc[2 * q + 1] += f0.y;
        }
    }
    uint4 yv = Y[node * 16 + l16];
#pragma unroll
    for (int q = 0; q < 4; q++) {
        uint32_t u = (&yv.x)[q];
        float2 f = __half22float2(*(__half2*)&u);
        float rx = acc[2 * q] + f.x;
        float ry = acc[2 * q + 1] + f.y;
        if (do_relu) { rx = fmaxf(rx, 0.f); ry = fmaxf(ry, 0.f); }
        out[node * 64 + l16 * 4 + q] = __floats2half2_rn(rx, ry);
    }
}

// ---------------- pooling (fp16 input) ----------------
__global__ void k_pool(const __half* __restrict__ h, const int* __restrict__ batch) {
    int base = blockIdx.x * 32;
    int col = threadIdx.x;
    int end = base + 32;
    if (end > N_NODES) end = N_NODES;
    if (base >= N_NODES) return;
    int cur = batch[base];
    float sum = 0.f;
    for (int n = base; n < end; n++) {
        int b = batch[n];
        if (b != cur) {
            atomicAdd(&g_pool[cur * HID + col], sum);
            sum = 0.f;
            cur = b;
        }
        sum += __half2float(h[n * HID + col]);
    }
    atomicAdd(&g_pool[cur * HID + col], sum);
}

// ---------------- output head ----------------
__global__ void k_out(const float* __restrict__ Wout, const float* __restrict__ bout,
                      float* __restrict__ out) {
    int t = threadIdx.x;
    if (t < NGRAPH * NCLASS) {
        int g = t / NCLASS;
        int c = t % NCLASS;
        float s = bout[c];
#pragma unroll 4
        for (int k = 0; k < HID; k++) s += g_pool[g * HID + k] * Wout[c * HID + k];
        out[t] = s;
    }
}

// ---------------- launch ----------------
extern "C" void kernel_launch(void* const* d_in, const int* in_sizes, int n_in,
                              void* d_out, int out_size) {
    const float* x = (const float*)d_in[0];
    const int* ei = (const int*)d_in[1];
    const int* src = ei;
    const int* dst = ei + N_EDGES;
    const int* batch = (const int*)d_in[2];
    const float* W1l = (const float*)d_in[3];
    const float* b1 = (const float*)d_in[4];
    const float* W1r = (const float*)d_in[5];
    const float* W2l = (const float*)d_in[6];
    const float* b2 = (const float*)d_in[7];
    const float* W2r = (const float*)d_in[8];
    const float* W3l = (const float*)d_in[9];
    const float* b3 = (const float*)d_in[10];
    const float* W3r = (const float*)d_in[11];
    const float* Wout = (const float*)d_in[12];
    const float* bout = (const float*)d_in[13];
    float* out = (float*)d_out;

    cudaFuncSetAttribute(k_projA, cudaFuncAttributeMaxDynamicSharedMemorySize, SMEM_P);
    cudaFuncSetAttribute(k_projH, cudaFuncAttributeMaxDynamicSharedMemorySize, SMEM_P);

    uint4* d_Z; cudaGetSymbolAddress((void**)&d_Z, g_Z);
    uint4* d_Y; cudaGetSymbolAddress((void**)&d_Y, g_Y);
    uint4* d_h; cudaGetSymbolAddress((void**)&d_h, g_h);
    uint4* d_B; cudaGetSymbolAddress((void**)&d_B, g_B);

    // prep (zero + weight round) then CSR build
    k_prep<<<(N_NODES + 255) / 256, 256>>>(W1l, W1r, W2l, W2r, W3l, W3r, (__half*)d_B);
    k_hist<<<(N_EDGES + 255) / 256, 256>>>(dst);
    k_scan1<<<SCAN_NB, 1024>>>();
    k_scan2<<<1, 1024>>>();
    k_scan3<<<(N_NODES + 255) / 256, 256>>>();
    k_scatter<<<(N_EDGES + 255) / 256, 256>>>(src, dst);

    // layer 1: x -> Z,Y -> h (relu)
    k_projA<<<PROJ_GRID, 256, SMEM_P>>>(x, d_B, b1, d_Z, d_Y);
    k_agg<<<(N_NODES / 2 + 7) / 8, 256>>>(d_Z, d_Y, (__half2*)d_h, 1);
    // layer 2
    k_projH<<<PROJ_GRID, 256, SMEM_P>>>(d_h, d_B + 4096, b2, d_Z, d_Y);
    k_agg<<<(N_NODES / 2 + 7) / 8, 256>>>(d_Z, d_Y, (__half2*)d_h, 1);
    // layer 3 (no relu)
    k_projH<<<PROJ_GRID, 256, SMEM_P>>>(d_h, d_B + 8192, b3, d_Z, d_Y);
    k_agg<<<(N_NODES / 2 + 7) / 8, 256>>>(d_Z, d_Y, (__half2*)d_h, 0);

    // pooling + head
    k_pool<<<(N_NODES + 31) / 32, 128>>>((const __half*)d_h, batch);
    k_out<<<1, 640>>>(Wout, bout, out);
}